// round 2
// baseline (speedup 1.0000x reference)
#include <cuda_runtime.h>
#include <math.h>

#define BS_    64
#define KK_    4
#define PTS_   5
#define RES_   28
#define STEPS_ 500
#define TC_    125      // t-chunk size
#define NCHUNK_ 4
#define NTHREADS_ 256
#define PIX_ (RES_*RES_)   // 784

typedef unsigned long long u64;

// staging: tanh-normed strokes per (b,k)
__device__ float g_stage[BS_ * KK_ * PIX_];
// per-batch arrival counters for fused compose (zero-init; reset each run)
__device__ unsigned int g_cnt[BS_];

__device__ __forceinline__ void fma2(u64 &d, u64 a, u64 b) {
    asm("fma.rn.f32x2 %0, %1, %2, %3;" : "=l"(d) : "l"(a), "l"(b), "l"(d));
}
__device__ __forceinline__ void unpack2(u64 v, float &lo, float &hi) {
    asm("mov.b64 {%0,%1}, %2;" : "=f"(lo), "=f"(hi) : "l"(v));
}

__global__ __launch_bounds__(NTHREADS_)
void guide_fused_kernel(const float* __restrict__ z_pres,
                        const float* __restrict__ z_what,
                        const float* __restrict__ z_where,
                        const float* __restrict__ sigma_p,
                        const float* __restrict__ slope_strk_p,
                        const float* __restrict__ slope_p,
                        float* __restrict__ out)
{
    // Ex: TC_*28 floats, Eyd: TC_*56 floats (duplicated pairs). 10500 floats = 42KB.
    // `part` (4*784+pad) aliases this buffer after the last chunk.
    __shared__ float sh[TC_ * RES_ + TC_ * 2 * RES_];
    __shared__ float red[8];
    __shared__ unsigned int slast;

    float* Ex  = sh;
    float* Eyd = sh + TC_ * RES_;

    const int bk  = blockIdx.x;           // 0..255 = b*4 + k
    const int tid = threadIdx.x;

    // ---- transform params (uniform) ----
    const float s   = z_where[bk * 3 + 0];
    const float sh0 = z_where[bk * 3 + 1];
    const float sh1 = z_where[bk * 3 + 2];

    float px0, px1, px2, px3, px4, py0, py1, py2, py3, py4;
    {
        const float* w = z_what + bk * PTS_ * 2;
        px0 = w[0] * s + sh0;  py0 = w[1] * s + sh1;
        px1 = w[2] * s + sh0;  py1 = w[3] * s + sh1;
        px2 = w[4] * s + sh0;  py2 = w[5] * s + sh1;
        px3 = w[6] * s + sh0;  py3 = w[7] * s + sh1;
        px4 = w[8] * s + sh0;  py4 = w[9] * s + sh1;
    }
    const float sigma = *sigma_p;
    const float ninv  = -1.0f / (2.0f * sigma * sigma);

    // phase-2 mapping: 4 t-groups x 49 tile-threads (7x7 tiles of 4x4 px)
    const int g   = tid >> 6;
    const int sid = tid & 63;
    const int ty  = sid / 7;
    const int tx  = sid - ty * 7;

    u64 acc[4][2];
#pragma unroll
    for (int i = 0; i < 4; i++) { acc[i][0] = 0ull; acc[i][1] = 0ull; }

    for (int c = 0; c < NCHUNK_; c++) {
        const int t0 = c * TC_;
        __syncthreads();   // previous chunk fully consumed before overwrite

        // ---- phase 1: fill Ex (plain) / Eyd (duplicated pairs) ----
        for (int w = tid; w < 2 * TC_; w += NTHREADS_) {
            const int tr  = w >> 1;
            const int isY = w & 1;
            const float u  = (float)(t0 + tr) * (1.0f / (float)(STEPS_ - 1));
            const float v  = 1.0f - u;
            const float u2 = u * u, v2 = v * v;
            const float b0 = v2 * v2;
            const float b1 = 4.0f * u * (v * v2);
            const float b2 = 6.0f * u2 * v2;
            const float b3 = 4.0f * (u2 * u) * v;
            const float b4 = u2 * u2;
            const float cx = b0*px0 + b1*px1 + b2*px2 + b3*px3 + b4*px4;
            const float cy = b0*py0 + b1*py1 + b2*py2 + b3*py3 + b4*py4;
            if (!isY) {
                const float cc = cx;
                float4* row4 = (float4*)(Ex + tr * RES_);
#pragma unroll
                for (int q = 0; q < 7; q++) {
                    float4 r;
                    float d0 = (float)(4*q + 0) * (1.0f/27.0f) - cc;
                    float d1 = (float)(4*q + 1) * (1.0f/27.0f) - cc;
                    float d2 = (float)(4*q + 2) * (1.0f/27.0f) - cc;
                    float d3 = (float)(4*q + 3) * (1.0f/27.0f) - cc;
                    r.x = __expf(d0 * d0 * ninv);
                    r.y = __expf(d1 * d1 * ninv);
                    r.z = __expf(d2 * d2 * ninv);
                    r.w = __expf(d3 * d3 * ninv);
                    row4[q] = r;
                }
            } else {
                const float cc = cy;
                float4* row4 = (float4*)(Eyd + tr * 2 * RES_);
#pragma unroll
                for (int q = 0; q < 14; q++) {
                    float d0 = (float)(2*q + 0) * (1.0f/27.0f) - cc;
                    float d1 = (float)(2*q + 1) * (1.0f/27.0f) - cc;
                    float e0 = __expf(d0 * d0 * ninv);
                    float e1 = __expf(d1 * d1 * ninv);
                    float4 r; r.x = e0; r.y = e0; r.z = e1; r.w = e1;
                    row4[q] = r;
                }
            }
        }
        __syncthreads();

        // ---- phase 2: rank-1 accumulation via packed f32x2 FMA ----
        if (sid < 49) {
            const int tl0 = (TC_ * g) >> 2;
            const int tl1 = (TC_ * (g + 1)) >> 2;
            const int exo = tx << 2;
            const int eyo = ty << 3;
#pragma unroll 4
            for (int tt = tl0; tt < tl1; tt++) {
                const ulonglong2 ex   = *(const ulonglong2*)(Ex  + tt * RES_ + exo);
                const ulonglong2 ey01 = *(const ulonglong2*)(Eyd + tt * 2 * RES_ + eyo);
                const ulonglong2 ey23 = *(const ulonglong2*)(Eyd + tt * 2 * RES_ + eyo + 4);
                fma2(acc[0][0], ey01.x, ex.x); fma2(acc[0][1], ey01.x, ex.y);
                fma2(acc[1][0], ey01.y, ex.x); fma2(acc[1][1], ey01.y, ex.y);
                fma2(acc[2][0], ey23.x, ex.x); fma2(acc[2][1], ey23.x, ex.y);
                fma2(acc[3][0], ey23.y, ex.x); fma2(acc[3][1], ey23.y, ex.y);
            }
        }
    }
    __syncthreads();

    // ---- merge 4 t-group partials (part aliases sh) ----
    float* part = sh;
    if (sid < 49) {
        float* pbase = part + g * PIX_;
#pragma unroll
        for (int i = 0; i < 4; i++) {
            float v0, v1, v2, v3;
            unpack2(acc[i][0], v0, v1);
            unpack2(acc[i][1], v2, v3);
            float* row = pbase + (ty * 4 + i) * RES_ + (tx * 4);
            row[0] = v0; row[1] = v1; row[2] = v2; row[3] = v3;
        }
    }
    __syncthreads();

    // ---- epilogue: z_pres scale, maxnorm, tanh-norm, stage ----
    const float zp = z_pres[bk];
    float myv[4];
    float lmax = 0.0f;
#pragma unroll
    for (int r = 0; r < 4; r++) {
        const int p = r * NTHREADS_ + tid;
        float v = 0.0f;
        if (p < PIX_) {
            v = (part[p] + part[PIX_ + p] + part[2*PIX_ + p] + part[3*PIX_ + p]) * zp;
        }
        myv[r] = v;
        lmax = fmaxf(lmax, v);
    }
#pragma unroll
    for (int o = 16; o > 0; o >>= 1)
        lmax = fmaxf(lmax, __shfl_xor_sync(0xffffffffu, lmax, o));
    if ((tid & 31) == 0) red[tid >> 5] = lmax;
    __syncthreads();
    float bmax = red[0];
#pragma unroll
    for (int w = 1; w < 8; w++) bmax = fmaxf(bmax, red[w]);

    const float scale = 1.0f / (bmax + 1e-6f);
    const float sl    = *slope_strk_p;
    const float itsl  = 1.0f / tanhf(sl);
    float* stage = g_stage + bk * PIX_;
#pragma unroll
    for (int r = 0; r < 4; r++) {
        const int p = r * NTHREADS_ + tid;
        if (p < PIX_)
            stage[p] = tanhf(myv[r] * scale * sl) * itsl;
    }

    // ---- fused compose: last CTA of each batch composes the image ----
    if (tid == 0) {
        __threadfence();   // publish stage writes before arrival
        unsigned int old = atomicAdd(&g_cnt[bk >> 2], 1u);
        slast = (old == 3u) ? 1u : 0u;
    }
    __syncthreads();
    if (slast) {
        __threadfence();   // acquire: see peer CTAs' stage writes
        const int b = bk >> 2;
        const float* st = g_stage + b * KK_ * PIX_;
        const float sl2  = *slope_p;
        const float it2  = 1.0f / tanhf(sl2);
        for (int p = tid; p < PIX_; p += NTHREADS_) {
            const float ssum = st[p] + st[PIX_ + p] + st[2*PIX_ + p] + st[3*PIX_ + p];
            out[b * PIX_ + p] = tanhf(ssum * sl2) * it2;
        }
        if (tid == 0) g_cnt[b] = 0u;   // reset for next (graph-replayed) call
    }
}

extern "C" void kernel_launch(void* const* d_in, const int* in_sizes, int n_in,
                              void* d_out, int out_size)
{
    const float* z_pres     = (const float*)d_in[0];
    const float* z_what     = (const float*)d_in[1];
    const float* z_where    = (const float*)d_in[2];
    const float* sigma      = (const float*)d_in[3];
    const float* slope_strk = (const float*)d_in[4];
    const float* slope      = (const float*)d_in[5];
    float* out = (float*)d_out;

    guide_fused_kernel<<<BS_ * KK_, NTHREADS_>>>(z_pres, z_what, z_where,
                                                 sigma, slope_strk, slope, out);
}

// round 3
// speedup vs baseline: 1.2073x; 1.2073x over previous
#include <cuda_runtime.h>
#include <math.h>

#define BS_    64
#define KK_    4
#define PTS_   5
#define RES_   28
#define STEPS_ 500
#define TC_    125      // t-chunk size
#define NCHUNK_ 4
#define NT_    512
#define NG_    8        // t-groups
#define PIX_ (RES_*RES_)   // 784

typedef unsigned long long u64;

// staging: tanh-normed strokes per (b,k)
__device__ float g_stage[BS_ * KK_ * PIX_];
// per-batch arrival counters for fused compose (zero-init; reset each run)
__device__ unsigned int g_cnt[BS_];

__device__ __forceinline__ void fma2(u64 &d, u64 a, u64 b) {
    asm("fma.rn.f32x2 %0, %1, %2, %3;" : "=l"(d) : "l"(a), "l"(b), "l"(d));
}
__device__ __forceinline__ u64 pack2(float v) {
    u64 r; asm("mov.b64 %0, {%1,%1};" : "=l"(r) : "f"(v)); return r;
}
__device__ __forceinline__ void unpack2(u64 v, float &lo, float &hi) {
    asm("mov.b64 {%0,%1}, %2;" : "=f"(lo), "=f"(hi) : "l"(v));
}

__global__ __launch_bounds__(NT_)
void guide_fused_kernel(const float* __restrict__ z_pres,
                        const float* __restrict__ z_what,
                        const float* __restrict__ z_where,
                        const float* __restrict__ sigma_p,
                        const float* __restrict__ slope_strk_p,
                        const float* __restrict__ slope_p,
                        float* __restrict__ out)
{
    // Ex: TC_*28, Ey: TC_*28 floats = 28KB. `part` (8*784=25KB) aliases after loop.
    __shared__ float sh[2 * TC_ * RES_];
    __shared__ float red[16];
    __shared__ unsigned int slast;

    float* Ex = sh;
    float* Ey = sh + TC_ * RES_;

    const int bk  = blockIdx.x;           // 0..255 = b*4 + k
    const int tid = threadIdx.x;

    // ---- transform params (uniform) ----
    const float s   = z_where[bk * 3 + 0];
    const float sh0 = z_where[bk * 3 + 1];
    const float sh1 = z_where[bk * 3 + 2];

    float px0, px1, px2, px3, px4, py0, py1, py2, py3, py4;
    {
        const float* w = z_what + bk * PTS_ * 2;
        px0 = w[0] * s + sh0;  py0 = w[1] * s + sh1;
        px1 = w[2] * s + sh0;  py1 = w[3] * s + sh1;
        px2 = w[4] * s + sh0;  py2 = w[5] * s + sh1;
        px3 = w[6] * s + sh0;  py3 = w[7] * s + sh1;
        px4 = w[8] * s + sh0;  py4 = w[9] * s + sh1;
    }
    const float sigma = *sigma_p;
    const float ninv  = -1.0f / (2.0f * sigma * sigma);

    // phase-2 mapping: 8 t-groups x 64 threads (49 active: 7x7 tiles of 4x4 px)
    const int g   = tid >> 6;     // 0..7
    const int sid = tid & 63;
    const int ty  = sid / 7;
    const int tx  = sid - ty * 7;
    const bool act = (sid < 49);

    u64 acc[4][2];
#pragma unroll
    for (int i = 0; i < 4; i++) { acc[i][0] = 0ull; acc[i][1] = 0ull; }

    for (int c = 0; c < NCHUNK_; c++) {
        const int t0 = c * TC_;
        __syncthreads();   // previous chunk fully consumed before overwrite

        // ---- phase 1: fill Ex / Ey rows ----
        if (tid < 2 * TC_) {
            const int tr  = tid >> 1;
            const int isY = tid & 1;
            const float u  = (float)(t0 + tr) * (1.0f / (float)(STEPS_ - 1));
            const float v  = 1.0f - u;
            const float u2 = u * u, v2 = v * v;
            const float b0 = v2 * v2;
            const float b1 = 4.0f * u * (v * v2);
            const float b2 = 6.0f * u2 * v2;
            const float b3 = 4.0f * (u2 * u) * v;
            const float b4 = u2 * u2;
            const float cx = b0*px0 + b1*px1 + b2*px2 + b3*px3 + b4*px4;
            const float cy = b0*py0 + b1*py1 + b2*py2 + b3*py3 + b4*py4;
            const float cc = isY ? cy : cx;
            float4* row4 = (float4*)((isY ? Ey : Ex) + tr * RES_);
#pragma unroll
            for (int q = 0; q < 7; q++) {
                float4 r;
                float d0 = (float)(4*q + 0) * (1.0f/27.0f) - cc;
                float d1 = (float)(4*q + 1) * (1.0f/27.0f) - cc;
                float d2 = (float)(4*q + 2) * (1.0f/27.0f) - cc;
                float d3 = (float)(4*q + 3) * (1.0f/27.0f) - cc;
                r.x = __expf(d0 * d0 * ninv);
                r.y = __expf(d1 * d1 * ninv);
                r.z = __expf(d2 * d2 * ninv);
                r.w = __expf(d3 * d3 * ninv);
                row4[q] = r;
            }
        }
        __syncthreads();

        // ---- phase 2: rank-1 accumulation; ex packed from LDS, ey dup'd in regs ----
        if (act) {
            const int tl0 = (TC_ * g) >> 3;
            const int tl1 = (TC_ * (g + 1)) >> 3;
            const ulonglong2* exp_ = (const ulonglong2*)(Ex + tl0 * RES_ + (tx << 2));
            const float4*     eyp  = (const float4*)(Ey + tl0 * RES_ + (ty << 2));
            const int stride = RES_ / 4;   // in float4/ulonglong2 units
#pragma unroll 4
            for (int tt = tl0; tt < tl1; tt++) {
                const ulonglong2 ex = *exp_;
                const float4     ey = *eyp;
                exp_ += stride; eyp += stride;
                const u64 ey0 = pack2(ey.x);
                const u64 ey1 = pack2(ey.y);
                const u64 ey2 = pack2(ey.z);
                const u64 ey3 = pack2(ey.w);
                fma2(acc[0][0], ey0, ex.x); fma2(acc[0][1], ey0, ex.y);
                fma2(acc[1][0], ey1, ex.x); fma2(acc[1][1], ey1, ex.y);
                fma2(acc[2][0], ey2, ex.x); fma2(acc[2][1], ey2, ex.y);
                fma2(acc[3][0], ey3, ex.x); fma2(acc[3][1], ey3, ex.y);
            }
        }
    }
    __syncthreads();

    // ---- merge 8 t-group partials (part aliases sh) ----
    float* part = sh;
    if (act) {
        float* pbase = part + g * PIX_;
#pragma unroll
        for (int i = 0; i < 4; i++) {
            float v0, v1, v2, v3;
            unpack2(acc[i][0], v0, v1);
            unpack2(acc[i][1], v2, v3);
            float* row = pbase + (ty * 4 + i) * RES_ + (tx * 4);
            row[0] = v0; row[1] = v1; row[2] = v2; row[3] = v3;
        }
    }
    __syncthreads();

    // ---- epilogue: z_pres scale, maxnorm, tanh-norm, stage ----
    const float zp = z_pres[bk];
    float myv[2];
    float lmax = 0.0f;
#pragma unroll
    for (int r = 0; r < 2; r++) {
        const int p = r * NT_ + tid;
        float v = 0.0f;
        if (p < PIX_) {
            v = part[p];
#pragma unroll
            for (int gg = 1; gg < NG_; gg++) v += part[gg * PIX_ + p];
            v *= zp;
        }
        myv[r] = v;
        lmax = fmaxf(lmax, v);
    }
#pragma unroll
    for (int o = 16; o > 0; o >>= 1)
        lmax = fmaxf(lmax, __shfl_xor_sync(0xffffffffu, lmax, o));
    if ((tid & 31) == 0) red[tid >> 5] = lmax;
    __syncthreads();
    float bmax = red[0];
#pragma unroll
    for (int w = 1; w < 16; w++) bmax = fmaxf(bmax, red[w]);

    const float scale = 1.0f / (bmax + 1e-6f);
    const float sl    = *slope_strk_p;
    const float itsl  = 1.0f / tanhf(sl);
    float* stage = g_stage + bk * PIX_;
#pragma unroll
    for (int r = 0; r < 2; r++) {
        const int p = r * NT_ + tid;
        if (p < PIX_)
            stage[p] = tanhf(myv[r] * scale * sl) * itsl;
    }

    // ---- fused compose: last CTA of each batch composes the image ----
    if (tid == 0) {
        __threadfence();   // publish stage writes before arrival
        unsigned int old = atomicAdd(&g_cnt[bk >> 2], 1u);
        slast = (old == 3u) ? 1u : 0u;
    }
    __syncthreads();
    if (slast) {
        __threadfence();   // acquire: see peer CTAs' stage writes
        const int b = bk >> 2;
        const float* st = g_stage + b * KK_ * PIX_;
        const float sl2 = *slope_p;
        const float it2 = 1.0f / tanhf(sl2);
        for (int p = tid; p < PIX_; p += NT_) {
            const float ssum = st[p] + st[PIX_ + p] + st[2*PIX_ + p] + st[3*PIX_ + p];
            out[b * PIX_ + p] = tanhf(ssum * sl2) * it2;
        }
        if (tid == 0) g_cnt[b] = 0u;   // reset for next (graph-replayed) call
    }
}

extern "C" void kernel_launch(void* const* d_in, const int* in_sizes, int n_in,
                              void* d_out, int out_size)
{
    const float* z_pres     = (const float*)d_in[0];
    const float* z_what     = (const float*)d_in[1];
    const float* z_where    = (const float*)d_in[2];
    const float* sigma      = (const float*)d_in[3];
    const float* slope_strk = (const float*)d_in[4];
    const float* slope      = (const float*)d_in[5];
    float* out = (float*)d_out;

    guide_fused_kernel<<<BS_ * KK_, NT_>>>(z_pres, z_what, z_where,
                                           sigma, slope_strk, slope, out);
}

// round 4
// speedup vs baseline: 1.3333x; 1.1044x over previous
#include <cuda_runtime.h>
#include <math.h>

#define BS_    64
#define KK_    4
#define PTS_   5
#define RES_   28
#define STEPS_ 500
#define TC_    250      // t-chunk size
#define NCHUNK_ 2
#define NT_    512
#define NG_    8        // t-groups
#define PIX_ (RES_*RES_)   // 784
#define SMEM_BYTES_ (2 * TC_ * RES_ * sizeof(float))   // 56000

typedef unsigned long long u64;

// staging: tanh-normed strokes per (b,k)
__device__ float g_stage[BS_ * KK_ * PIX_];
// per-batch arrival counters for fused compose (zero-init; reset each run)
__device__ unsigned int g_cnt[BS_];

__device__ __forceinline__ void fma2(u64 &d, u64 a, u64 b) {
    asm("fma.rn.f32x2 %0, %1, %2, %3;" : "=l"(d) : "l"(a), "l"(b), "l"(d));
}
__device__ __forceinline__ u64 pack2(float v) {
    u64 r; asm("mov.b64 %0, {%1,%1};" : "=l"(r) : "f"(v)); return r;
}
__device__ __forceinline__ void unpack2(u64 v, float &lo, float &hi) {
    asm("mov.b64 {%0,%1}, %2;" : "=f"(lo), "=f"(hi) : "l"(v));
}

__global__ __launch_bounds__(NT_, 2)
void guide_fused_kernel(const float* __restrict__ z_pres,
                        const float* __restrict__ z_what,
                        const float* __restrict__ z_where,
                        const float* __restrict__ sigma_p,
                        const float* __restrict__ slope_strk_p,
                        const float* __restrict__ slope_p,
                        float* __restrict__ out)
{
    extern __shared__ float sh[];      // Ex[TC_*28] | Ey[TC_*28]; part aliases
    __shared__ float red[16];
    __shared__ unsigned int slast;

    float* Ex = sh;
    float* Ey = sh + TC_ * RES_;

    const int bk  = blockIdx.x;           // 0..255 = b*4 + k
    const int tid = threadIdx.x;

    // ---- transform params (uniform) ----
    const float s   = z_where[bk * 3 + 0];
    const float sh0 = z_where[bk * 3 + 1];
    const float sh1 = z_where[bk * 3 + 2];

    float px0, px1, px2, px3, px4, py0, py1, py2, py3, py4;
    {
        const float* w = z_what + bk * PTS_ * 2;
        px0 = w[0] * s + sh0;  py0 = w[1] * s + sh1;
        px1 = w[2] * s + sh0;  py1 = w[3] * s + sh1;
        px2 = w[4] * s + sh0;  py2 = w[5] * s + sh1;
        px3 = w[6] * s + sh0;  py3 = w[7] * s + sh1;
        px4 = w[8] * s + sh0;  py4 = w[9] * s + sh1;
    }
    const float sigma = *sigma_p;
    const float ninv  = -1.0f / (2.0f * sigma * sigma);

    // phase-2 mapping: 8 t-groups x 64 threads (49 active: 7x7 tiles of 4x4 px)
    const int g   = tid >> 6;     // 0..7
    const int sid = tid & 63;
    const int ty  = sid / 7;
    const int tx  = sid - ty * 7;
    const bool act = (sid < 49);

    u64 acc[4][2];
#pragma unroll
    for (int i = 0; i < 4; i++) { acc[i][0] = 0ull; acc[i][1] = 0ull; }

#pragma unroll
    for (int c = 0; c < NCHUNK_; c++) {
        const int t0 = c * TC_;
        __syncthreads();   // previous chunk fully consumed before overwrite

        // ---- phase 1: fill Ex / Ey rows (500 tasks, ~all threads) ----
        if (tid < 2 * TC_) {
            const int tr  = tid >> 1;
            const int isY = tid & 1;
            const float u  = (float)(t0 + tr) * (1.0f / (float)(STEPS_ - 1));
            const float v  = 1.0f - u;
            const float u2 = u * u, v2 = v * v;
            const float b0 = v2 * v2;
            const float b1 = 4.0f * u * (v * v2);
            const float b2 = 6.0f * u2 * v2;
            const float b3 = 4.0f * (u2 * u) * v;
            const float b4 = u2 * u2;
            const float cx = b0*px0 + b1*px1 + b2*px2 + b3*px3 + b4*px4;
            const float cy = b0*py0 + b1*py1 + b2*py2 + b3*py3 + b4*py4;
            const float cc = isY ? cy : cx;
            float4* row4 = (float4*)((isY ? Ey : Ex) + tr * RES_);
#pragma unroll
            for (int q = 0; q < 7; q++) {
                float4 r;
                float d0 = (float)(4*q + 0) * (1.0f/27.0f) - cc;
                float d1 = (float)(4*q + 1) * (1.0f/27.0f) - cc;
                float d2 = (float)(4*q + 2) * (1.0f/27.0f) - cc;
                float d3 = (float)(4*q + 3) * (1.0f/27.0f) - cc;
                r.x = __expf(d0 * d0 * ninv);
                r.y = __expf(d1 * d1 * ninv);
                r.z = __expf(d2 * d2 * ninv);
                r.w = __expf(d3 * d3 * ninv);
                row4[q] = r;
            }
        }
        __syncthreads();

        // ---- phase 2: rank-1 accumulation, 2-iter batched loads ----
        if (act) {
            const int tl0 = (TC_ * g) >> 3;
            const int tl1 = (TC_ * (g + 1)) >> 3;
            const char* exp_ = (const char*)(Ex + tl0 * RES_ + (tx << 2));
            const char* eyp_ = (const char*)(Ey + tl0 * RES_ + (ty << 2));
            int n = tl1 - tl0;
#pragma unroll 1
            for (; n >= 2; n -= 2) {
                const ulonglong2 ex0 = *(const ulonglong2*)(exp_);
                const float4     ey0 = *(const float4*)(eyp_);
                const ulonglong2 ex1 = *(const ulonglong2*)(exp_ + RES_ * 4);
                const float4     ey1 = *(const float4*)(eyp_ + RES_ * 4);
                exp_ += RES_ * 8; eyp_ += RES_ * 8;
                {
                    const u64 a0 = pack2(ey0.x), a1 = pack2(ey0.y);
                    const u64 a2 = pack2(ey0.z), a3 = pack2(ey0.w);
                    fma2(acc[0][0], a0, ex0.x); fma2(acc[0][1], a0, ex0.y);
                    fma2(acc[1][0], a1, ex0.x); fma2(acc[1][1], a1, ex0.y);
                    fma2(acc[2][0], a2, ex0.x); fma2(acc[2][1], a2, ex0.y);
                    fma2(acc[3][0], a3, ex0.x); fma2(acc[3][1], a3, ex0.y);
                }
                {
                    const u64 a0 = pack2(ey1.x), a1 = pack2(ey1.y);
                    const u64 a2 = pack2(ey1.z), a3 = pack2(ey1.w);
                    fma2(acc[0][0], a0, ex1.x); fma2(acc[0][1], a0, ex1.y);
                    fma2(acc[1][0], a1, ex1.x); fma2(acc[1][1], a1, ex1.y);
                    fma2(acc[2][0], a2, ex1.x); fma2(acc[2][1], a2, ex1.y);
                    fma2(acc[3][0], a3, ex1.x); fma2(acc[3][1], a3, ex1.y);
                }
            }
            if (n) {
                const ulonglong2 ex0 = *(const ulonglong2*)(exp_);
                const float4     ey0 = *(const float4*)(eyp_);
                const u64 a0 = pack2(ey0.x), a1 = pack2(ey0.y);
                const u64 a2 = pack2(ey0.z), a3 = pack2(ey0.w);
                fma2(acc[0][0], a0, ex0.x); fma2(acc[0][1], a0, ex0.y);
                fma2(acc[1][0], a1, ex0.x); fma2(acc[1][1], a1, ex0.y);
                fma2(acc[2][0], a2, ex0.x); fma2(acc[2][1], a2, ex0.y);
                fma2(acc[3][0], a3, ex0.x); fma2(acc[3][1], a3, ex0.y);
            }
        }
    }
    __syncthreads();

    // ---- merge 8 t-group partials (part aliases sh) ----
    float* part = sh;
    if (act) {
        float* pbase = part + g * PIX_;
#pragma unroll
        for (int i = 0; i < 4; i++) {
            float v0, v1, v2, v3;
            unpack2(acc[i][0], v0, v1);
            unpack2(acc[i][1], v2, v3);
            float* row = pbase + (ty * 4 + i) * RES_ + (tx * 4);
            row[0] = v0; row[1] = v1; row[2] = v2; row[3] = v3;
        }
    }
    __syncthreads();

    // ---- epilogue: z_pres scale, maxnorm, tanh-norm, stage ----
    const float zp = z_pres[bk];
    float myv[2];
    float lmax = 0.0f;
#pragma unroll
    for (int r = 0; r < 2; r++) {
        const int p = r * NT_ + tid;
        float v = 0.0f;
        if (p < PIX_) {
            v = part[p];
#pragma unroll
            for (int gg = 1; gg < NG_; gg++) v += part[gg * PIX_ + p];
            v *= zp;
        }
        myv[r] = v;
        lmax = fmaxf(lmax, v);
    }
#pragma unroll
    for (int o = 16; o > 0; o >>= 1)
        lmax = fmaxf(lmax, __shfl_xor_sync(0xffffffffu, lmax, o));
    if ((tid & 31) == 0) red[tid >> 5] = lmax;
    __syncthreads();
    float bmax = red[0];
#pragma unroll
    for (int w = 1; w < 16; w++) bmax = fmaxf(bmax, red[w]);

    const float scale = 1.0f / (bmax + 1e-6f);
    const float sl    = *slope_strk_p;
    const float itsl  = 1.0f / tanhf(sl);
    float* stage = g_stage + bk * PIX_;
#pragma unroll
    for (int r = 0; r < 2; r++) {
        const int p = r * NT_ + tid;
        if (p < PIX_)
            stage[p] = tanhf(myv[r] * scale * sl) * itsl;
    }

    // ---- fused compose: last CTA of each batch composes the image ----
    if (tid == 0) {
        __threadfence();   // publish stage writes before arrival
        unsigned int old = atomicAdd(&g_cnt[bk >> 2], 1u);
        slast = (old == 3u) ? 1u : 0u;
    }
    __syncthreads();
    if (slast) {
        __threadfence();   // acquire: see peer CTAs' stage writes
        const int b = bk >> 2;
        const float* st = g_stage + b * KK_ * PIX_;
        const float sl2 = *slope_p;
        const float it2 = 1.0f / tanhf(sl2);
        for (int p = tid; p < PIX_; p += NT_) {
            const float ssum = st[p] + st[PIX_ + p] + st[2*PIX_ + p] + st[3*PIX_ + p];
            out[b * PIX_ + p] = tanhf(ssum * sl2) * it2;
        }
        if (tid == 0) g_cnt[b] = 0u;   // reset for next (graph-replayed) call
    }
}

extern "C" void kernel_launch(void* const* d_in, const int* in_sizes, int n_in,
                              void* d_out, int out_size)
{
    const float* z_pres     = (const float*)d_in[0];
    const float* z_what     = (const float*)d_in[1];
    const float* z_where    = (const float*)d_in[2];
    const float* sigma      = (const float*)d_in[3];
    const float* slope_strk = (const float*)d_in[4];
    const float* slope      = (const float*)d_in[5];
    float* out = (float*)d_out;

    cudaFuncSetAttribute(guide_fused_kernel,
                         cudaFuncAttributeMaxDynamicSharedMemorySize,
                         (int)SMEM_BYTES_);
    guide_fused_kernel<<<BS_ * KK_, NT_, SMEM_BYTES_>>>(z_pres, z_what, z_where,
                                                        sigma, slope_strk, slope, out);
}